// round 12
// baseline (speedup 1.0000x reference)
#include <cuda_runtime.h>

// EquivariantLayerNorm, specialized to IRREPS=[(256,0),(128,1),(64,2),(32,3)]
//   dim = 1184, f4-per-row = 296
//   f4 group ranges: g0 [0,64) g1 [64,160) g2 [160,240) g3 [240,296)
//   element counts: 256, 384, 320, 224; scalar block = g0, identity bias map.
//
// Barrier-free warp-per-group (round-9 body), with PROPORTIONAL warp counts
// and per-group atomic row-block queues so all warps do identical total work
// (4096 f4) and all queues drain at the same time (no heavy-warp tail):
//   grid = 1184 CTAs x 4 warps = 4736 warps = 16 x 296
//   g0: 1024 warps, g1: 1536, g2: 1280, g3: 896   (16 * group_f4)
//   block = 4 contiguous rows; next block grabbed one block early.

#define DIM   1184
#define EPSV  1e-5f
#define BLK   4

__device__ int g_ctr[4];     // zeroed via cudaMemsetAsync before each launch

__global__ __launch_bounds__(128) void eln_kernel(const float* __restrict__ x,
                                                  float* __restrict__ out,
                                                  const float* __restrict__ weight,
                                                  const float* __restrict__ bias,
                                                  const int* __restrict__ irrep_idx,
                                                  int nrows) {
    const int warp = threadIdx.x >> 5;
    const int lane = threadIdx.x & 31;
    const int gw   = blockIdx.x * 4 + warp;     // global warp id [0, 4736)

    // ---- proportional warp->group assignment (init only; warp-uniform) ----
    int g, k, Ngw;
    if (gw < 1024)      { g = 0; k = gw;        Ngw = 1024; }
    else if (gw < 2560) { g = 1; k = gw - 1024; Ngw = 1536; }
    else if (gw < 3840) { g = 2; k = gw - 2560; Ngw = 1280; }
    else                { g = 3; k = gw - 3840; Ngw = 896;  }

    int s0, sz; float inv;
    if (g == 0)      { s0 = 0;   sz = 64; inv = 1.f / 256.f; }
    else if (g == 1) { s0 = 64;  sz = 96; inv = 1.f / 384.f; }
    else if (g == 2) { s0 = 160; sz = 80; inv = 1.f / 320.f; }
    else             { s0 = 240; sz = 56; inv = 1.f / 224.f; }
    const bool isScalar = (g == 0);

    const int  i0 = s0 + lane;                 // always valid
    const bool p1 = (lane + 32) < sz;
    const bool p2 = (lane + 64) < sz;
    const int  i1 = i0 + 32;
    const int  i2 = i0 + 64;

    // ---- one-time init: per-slot weight / bias in registers ----
    float4 w0 = make_float4(0.f,0.f,0.f,0.f), w1 = w0, w2 = w0;
    {
        const int c = 4 * i0;
        w0.x = weight[irrep_idx[c+0]]; w0.y = weight[irrep_idx[c+1]];
        w0.z = weight[irrep_idx[c+2]]; w0.w = weight[irrep_idx[c+3]];
    }
    if (p1) {
        const int c = 4 * i1;
        w1.x = weight[irrep_idx[c+0]]; w1.y = weight[irrep_idx[c+1]];
        w1.z = weight[irrep_idx[c+2]]; w1.w = weight[irrep_idx[c+3]];
    }
    if (p2) {
        const int c = 4 * i2;
        w2.x = weight[irrep_idx[c+0]]; w2.y = weight[irrep_idx[c+1]];
        w2.z = weight[irrep_idx[c+2]]; w2.w = weight[irrep_idx[c+3]];
    }
    float4 b0 = make_float4(0.f,0.f,0.f,0.f), b1 = b0;
    if (isScalar) {   // scalar block = cols [0,256) = g0's two slots, identity map
        b0 = ((const float4*)bias)[i0];
        b1 = ((const float4*)bias)[i1];
    }

    const int NBLK = nrows / BLK;              // 16384

    // First block is static (k); subsequent blocks come from the group queue,
    // offset by Ngw so the counter starts at 0 after the memset.
    int blk = k;

    float4 v0 = make_float4(0.f,0.f,0.f,0.f), v1 = v0, v2 = v0;
    if (blk < NBLK) {
        const float4* xr = (const float4*)(x + (size_t)(blk * BLK) * DIM);
        v0 = __ldcs(xr + i0);
        if (p1) v1 = __ldcs(xr + i1);
        if (p2) v2 = __ldcs(xr + i2);
    }

    while (blk < NBLK) {
        // Grab next block early (atomic latency hidden under this block's work).
        int nblk;
        if (lane == 0) nblk = Ngw + atomicAdd(&g_ctr[g], 1);
        nblk = __shfl_sync(0xffffffffu, nblk, 0);

        #pragma unroll
        for (int j = 0; j < BLK; j++) {
            const int row = blk * BLK + j;

            float q = v0.x*v0.x + v0.y*v0.y + v0.z*v0.z + v0.w*v0.w
                    + v1.x*v1.x + v1.y*v1.y + v1.z*v1.z + v1.w*v1.w
                    + v2.x*v2.x + v2.y*v2.y + v2.z*v2.z + v2.w*v2.w;
            float s = isScalar ? (v0.x + v0.y + v0.z + v0.w +
                                  v1.x + v1.y + v1.z + v1.w) : 0.f;

            // Prefetch next row (within block, or first row of next block).
            const int  nrow   = (j < BLK - 1) ? (row + 1) : (nblk * BLK);
            const bool nvalid = (j < BLK - 1) || (nblk < NBLK);
            float4 nv0 = make_float4(0.f,0.f,0.f,0.f), nv1 = nv0, nv2 = nv0;
            if (nvalid) {
                const float4* nxr = (const float4*)(x + (size_t)nrow * DIM);
                nv0 = __ldcs(nxr + i0);
                if (p1) nv1 = __ldcs(nxr + i1);
                if (p2) nv2 = __ldcs(nxr + i2);
            }

            #pragma unroll
            for (int off = 16; off; off >>= 1) {
                q += __shfl_xor_sync(0xffffffffu, q, off);
                s += __shfl_xor_sync(0xffffffffu, s, off);
            }

            const float m  = s * inv;                   // 0 for non-scalar warps
            const float rn = rsqrtf(q * inv - m * m + EPSV);

            float4* orow = (float4*)(out + (size_t)row * DIM);
            {
                float4 o;
                o.x = (v0.x - m) * rn * w0.x + b0.x;
                o.y = (v0.y - m) * rn * w0.y + b0.y;
                o.z = (v0.z - m) * rn * w0.z + b0.z;
                o.w = (v0.w - m) * rn * w0.w + b0.w;
                __stcs(orow + i0, o);
            }
            if (p1) {
                float4 o;
                o.x = (v1.x - m) * rn * w1.x + b1.x;
                o.y = (v1.y - m) * rn * w1.y + b1.y;
                o.z = (v1.z - m) * rn * w1.z + b1.z;
                o.w = (v1.w - m) * rn * w1.w + b1.w;
                __stcs(orow + i1, o);
            }
            if (p2) {
                float4 o;
                o.x = v2.x * rn * w2.x;                 // slot2 never scalar: m=0, b=0
                o.y = v2.y * rn * w2.y;
                o.z = v2.z * rn * w2.z;
                o.w = v2.w * rn * w2.w;
                __stcs(orow + i2, o);
            }

            v0 = nv0; v1 = nv1; v2 = nv2;
        }
        blk = nblk;
    }
}

extern "C" void kernel_launch(void* const* d_in, const int* in_sizes, int n_in,
                              void* d_out, int out_size) {
    const float* x         = (const float*)d_in[0];
    const float* weight    = (const float*)d_in[1];
    const float* bias      = (const float*)d_in[2];
    const int*   irrep_idx = (const int*)  d_in[4];

    const int dim = in_sizes[3];           // 1184
    const int n   = in_sizes[0] / dim;     // 65536 rows

    void* ctr_addr = nullptr;
    cudaGetSymbolAddress(&ctr_addr, g_ctr);
    cudaMemsetAsync(ctr_addr, 0, 4 * sizeof(int));

    eln_kernel<<<1184, 128>>>(x, (float*)d_out, weight, bias, irrep_idx, n);
}

// round 13
// speedup vs baseline: 1.4740x; 1.4740x over previous
#include <cuda_runtime.h>

// EquivariantLayerNorm, specialized to IRREPS=[(256,0),(128,1),(64,2),(32,3)]
//   dim = 1184, f4-per-row = 296
//   f4 group ranges: g0 [0,64) g1 [64,160) g2 [160,240) g3 [240,296)
//   element counts: 256, 384, 320, 224; scalar block = g0, identity bias map.
//
// Round-9 proven design (barrier-free, warp-per-group, rotated assignment,
// 1-deep prefetch) with 9 CTAs/SM instead of 8: grid 1332 = 148*9,
// __launch_bounds__(128, 9) pins regs at 56 (what the kernel already uses).

#define DIM   1184
#define EPSV  1e-5f
#define GRID  (148 * 9)

__global__ __launch_bounds__(128, 9) void eln_kernel(const float* __restrict__ x,
                                                     float* __restrict__ out,
                                                     const float* __restrict__ weight,
                                                     const float* __restrict__ bias,
                                                     const int* __restrict__ irrep_idx,
                                                     int nrows) {
    const int t    = threadIdx.x;
    const int warp = t >> 5;
    const int lane = t & 31;
    const int g    = (warp + blockIdx.x) & 3;   // rotated group assignment

    // ---- per-warp group parameters (init only; warp-uniform) ----
    int s0, sz; float inv;
    if (g == 0)      { s0 = 0;   sz = 64; inv = 1.f / 256.f; }
    else if (g == 1) { s0 = 64;  sz = 96; inv = 1.f / 384.f; }
    else if (g == 2) { s0 = 160; sz = 80; inv = 1.f / 320.f; }
    else             { s0 = 240; sz = 56; inv = 1.f / 224.f; }
    const bool isScalar = (g == 0);

    const int  i0 = s0 + lane;                 // always valid
    const bool p1 = (lane + 32) < sz;
    const bool p2 = (lane + 64) < sz;
    const int  i1 = i0 + 32;
    const int  i2 = i0 + 64;

    // ---- one-time init: per-slot weight / bias in registers ----
    float4 w0 = make_float4(0.f,0.f,0.f,0.f), w1 = w0, w2 = w0;
    {
        const int c = 4 * i0;
        w0.x = weight[irrep_idx[c+0]]; w0.y = weight[irrep_idx[c+1]];
        w0.z = weight[irrep_idx[c+2]]; w0.w = weight[irrep_idx[c+3]];
    }
    if (p1) {
        const int c = 4 * i1;
        w1.x = weight[irrep_idx[c+0]]; w1.y = weight[irrep_idx[c+1]];
        w1.z = weight[irrep_idx[c+2]]; w1.w = weight[irrep_idx[c+3]];
    }
    if (p2) {
        const int c = 4 * i2;
        w2.x = weight[irrep_idx[c+0]]; w2.y = weight[irrep_idx[c+1]];
        w2.z = weight[irrep_idx[c+2]]; w2.w = weight[irrep_idx[c+3]];
    }
    float4 b0 = make_float4(0.f,0.f,0.f,0.f), b1 = b0;
    if (isScalar) {   // scalar block = cols [0,256) = g0's two slots, identity map
        b0 = ((const float4*)bias)[i0];
        b1 = ((const float4*)bias)[i1];
    }

    int row = blockIdx.x;
    const int stride = gridDim.x;

    float4 v0 = make_float4(0.f,0.f,0.f,0.f), v1 = v0, v2 = v0;
    if (row < nrows) {
        const float4* xr = (const float4*)(x + (size_t)row * DIM);
        v0 = __ldcs(xr + i0);
        if (p1) v1 = __ldcs(xr + i1);
        if (p2) v2 = __ldcs(xr + i2);
    }

    while (row < nrows) {
        float q = v0.x*v0.x + v0.y*v0.y + v0.z*v0.z + v0.w*v0.w
                + v1.x*v1.x + v1.y*v1.y + v1.z*v1.z + v1.w*v1.w
                + v2.x*v2.x + v2.y*v2.y + v2.z*v2.z + v2.w*v2.w;
        float s = isScalar ? (v0.x + v0.y + v0.z + v0.w +
                              v1.x + v1.y + v1.z + v1.w) : 0.f;

        // Prefetch next row while the shuffles run.
        const int nrow = row + stride;
        float4 nv0 = make_float4(0.f,0.f,0.f,0.f), nv1 = nv0, nv2 = nv0;
        if (nrow < nrows) {
            const float4* nxr = (const float4*)(x + (size_t)nrow * DIM);
            nv0 = __ldcs(nxr + i0);
            if (p1) nv1 = __ldcs(nxr + i1);
            if (p2) nv2 = __ldcs(nxr + i2);
        }

        #pragma unroll
        for (int off = 16; off; off >>= 1) {
            q += __shfl_xor_sync(0xffffffffu, q, off);
            s += __shfl_xor_sync(0xffffffffu, s, off);
        }

        const float m  = s * inv;                       // 0 for non-scalar warps
        const float rn = rsqrtf(q * inv - m * m + EPSV);

        float4* orow = (float4*)(out + (size_t)row * DIM);
        {
            float4 o;
            o.x = (v0.x - m) * rn * w0.x + b0.x;
            o.y = (v0.y - m) * rn * w0.y + b0.y;
            o.z = (v0.z - m) * rn * w0.z + b0.z;
            o.w = (v0.w - m) * rn * w0.w + b0.w;
            __stcs(orow + i0, o);
        }
        if (p1) {
            float4 o;
            o.x = (v1.x - m) * rn * w1.x + b1.x;
            o.y = (v1.y - m) * rn * w1.y + b1.y;
            o.z = (v1.z - m) * rn * w1.z + b1.z;
            o.w = (v1.w - m) * rn * w1.w + b1.w;
            __stcs(orow + i1, o);
        }
        if (p2) {
            float4 o;
            o.x = v2.x * rn * w2.x;                     // slot2 never scalar: m=0, b=0
            o.y = v2.y * rn * w2.y;
            o.z = v2.z * rn * w2.z;
            o.w = v2.w * rn * w2.w;
            __stcs(orow + i2, o);
        }

        v0 = nv0; v1 = nv1; v2 = nv2;
        row = nrow;
    }
}

extern "C" void kernel_launch(void* const* d_in, const int* in_sizes, int n_in,
                              void* d_out, int out_size) {
    const float* x         = (const float*)d_in[0];
    const float* weight    = (const float*)d_in[1];
    const float* bias      = (const float*)d_in[2];
    const int*   irrep_idx = (const int*)  d_in[4];

    const int dim = in_sizes[3];           // 1184
    const int n   = in_sizes[0] / dim;     // 65536 rows

    eln_kernel<<<GRID, 128>>>(x, (float*)d_out, weight, bias, irrep_idx, n);
}

// round 14
// speedup vs baseline: 1.4806x; 1.0045x over previous
#include <cuda_runtime.h>

// EquivariantLayerNorm, specialized to IRREPS=[(256,0),(128,1),(64,2),(32,3)]
//   dim = 1184, f4-per-row = 296
//   f4 group ranges: g0 [0,64) g1 [64,160) g2 [160,240) g3 [240,296)
//   element counts: 256, 384, 320, 224; scalar block = g0, identity bias map.
//
// Round-9 proven config (barrier-free warp-per-group, rotated assignment,
// grid 148*8, 1-deep register prefetch) + prefetch.global.L2 hints for row
// i+2*stride: DRAM latency moved off the critical path at zero register cost.

#define DIM   1184
#define EPSV  1e-5f

__global__ __launch_bounds__(128) void eln_kernel(const float* __restrict__ x,
                                                  float* __restrict__ out,
                                                  const float* __restrict__ weight,
                                                  const float* __restrict__ bias,
                                                  const int* __restrict__ irrep_idx,
                                                  int nrows) {
    const int t    = threadIdx.x;
    const int warp = t >> 5;
    const int lane = t & 31;
    const int g    = (warp + blockIdx.x) & 3;   // rotated group assignment

    // ---- per-warp group parameters (init only; warp-uniform) ----
    int s0, sz; float inv;
    if (g == 0)      { s0 = 0;   sz = 64; inv = 1.f / 256.f; }
    else if (g == 1) { s0 = 64;  sz = 96; inv = 1.f / 384.f; }
    else if (g == 2) { s0 = 160; sz = 80; inv = 1.f / 320.f; }
    else             { s0 = 240; sz = 56; inv = 1.f / 224.f; }
    const bool isScalar = (g == 0);

    const int  i0 = s0 + lane;                 // always valid
    const bool p1 = (lane + 32) < sz;
    const bool p2 = (lane + 64) < sz;
    const int  i1 = i0 + 32;
    const int  i2 = i0 + 64;

    // ---- one-time init: per-slot weight / bias in registers ----
    float4 w0 = make_float4(0.f,0.f,0.f,0.f), w1 = w0, w2 = w0;
    {
        const int c = 4 * i0;
        w0.x = weight[irrep_idx[c+0]]; w0.y = weight[irrep_idx[c+1]];
        w0.z = weight[irrep_idx[c+2]]; w0.w = weight[irrep_idx[c+3]];
    }
    if (p1) {
        const int c = 4 * i1;
        w1.x = weight[irrep_idx[c+0]]; w1.y = weight[irrep_idx[c+1]];
        w1.z = weight[irrep_idx[c+2]]; w1.w = weight[irrep_idx[c+3]];
    }
    if (p2) {
        const int c = 4 * i2;
        w2.x = weight[irrep_idx[c+0]]; w2.y = weight[irrep_idx[c+1]];
        w2.z = weight[irrep_idx[c+2]]; w2.w = weight[irrep_idx[c+3]];
    }
    float4 b0 = make_float4(0.f,0.f,0.f,0.f), b1 = b0;
    if (isScalar) {   // scalar block = cols [0,256) = g0's two slots, identity map
        b0 = ((const float4*)bias)[i0];
        b1 = ((const float4*)bias)[i1];
    }

    int row = blockIdx.x;
    const int    stride = gridDim.x;
    const size_t stepF4 = (size_t)stride * (DIM / 4);   // f4 elements per stride

    float4 v0 = make_float4(0.f,0.f,0.f,0.f), v1 = v0, v2 = v0;
    if (row < nrows) {
        const float4* xr = (const float4*)(x + (size_t)row * DIM);
        v0 = __ldcs(xr + i0);
        if (p1) v1 = __ldcs(xr + i1);
        if (p2) v2 = __ldcs(xr + i2);
    }

    while (row < nrows) {
        float q = v0.x*v0.x + v0.y*v0.y + v0.z*v0.z + v0.w*v0.w
                + v1.x*v1.x + v1.y*v1.y + v1.z*v1.z + v1.w*v1.w
                + v2.x*v2.x + v2.y*v2.y + v2.z*v2.z + v2.w*v2.w;
        float s = isScalar ? (v0.x + v0.y + v0.z + v0.w +
                              v1.x + v1.y + v1.z + v1.w) : 0.f;

        // Prefetch next row into registers while the shuffles run.
        const int nrow = row + stride;
        float4 nv0 = make_float4(0.f,0.f,0.f,0.f), nv1 = nv0, nv2 = nv0;
        if (nrow < nrows) {
            const float4* nxr = (const float4*)(x + (size_t)nrow * DIM);
            nv0 = __ldcs(nxr + i0);
            if (p1) nv1 = __ldcs(nxr + i1);
            if (p2) nv2 = __ldcs(nxr + i2);
            // L2 prefetch hint for row + 2*stride: zero register cost, moves
            // next iteration's demand load from DRAM latency to L2-hit latency.
            if (nrow + stride < nrows) {
                const float4* fxr = nxr + stepF4;
                asm volatile("prefetch.global.L2 [%0];" :: "l"(fxr + i0));
                if (p1) asm volatile("prefetch.global.L2 [%0];" :: "l"(fxr + i1));
                if (p2) asm volatile("prefetch.global.L2 [%0];" :: "l"(fxr + i2));
            }
        }

        #pragma unroll
        for (int off = 16; off; off >>= 1) {
            q += __shfl_xor_sync(0xffffffffu, q, off);
            s += __shfl_xor_sync(0xffffffffu, s, off);
        }

        const float m  = s * inv;                       // 0 for non-scalar warps
        const float rn = rsqrtf(q * inv - m * m + EPSV);

        float4* orow = (float4*)(out + (size_t)row * DIM);
        {
            float4 o;
            o.x = (v0.x - m) * rn * w0.x + b0.x;
            o.y = (v0.y - m) * rn * w0.y + b0.y;
            o.z = (v0.z - m) * rn * w0.z + b0.z;
            o.w = (v0.w - m) * rn * w0.w + b0.w;
            __stcs(orow + i0, o);
        }
        if (p1) {
            float4 o;
            o.x = (v1.x - m) * rn * w1.x + b1.x;
            o.y = (v1.y - m) * rn * w1.y + b1.y;
            o.z = (v1.z - m) * rn * w1.z + b1.z;
            o.w = (v1.w - m) * rn * w1.w + b1.w;
            __stcs(orow + i1, o);
        }
        if (p2) {
            float4 o;
            o.x = v2.x * rn * w2.x;                     // slot2 never scalar: m=0, b=0
            o.y = v2.y * rn * w2.y;
            o.z = v2.z * rn * w2.z;
            o.w = v2.w * rn * w2.w;
            __stcs(orow + i2, o);
        }

        v0 = nv0; v1 = nv1; v2 = nv2;
        row = nrow;
    }
}

extern "C" void kernel_launch(void* const* d_in, const int* in_sizes, int n_in,
                              void* d_out, int out_size) {
    const float* x         = (const float*)d_in[0];
    const float* weight    = (const float*)d_in[1];
    const float* bias      = (const float*)d_in[2];
    const int*   irrep_idx = (const int*)  d_in[4];

    const int dim = in_sizes[3];           // 1184
    const int n   = in_sizes[0] / dim;     // 65536 rows

    const int grid = 148 * 8;              // proven optimum: 8 CTAs/SM
    eln_kernel<<<grid, 128>>>(x, (float*)d_out, weight, bias, irrep_idx, n);
}

// round 15
// speedup vs baseline: 1.4995x; 1.0128x over previous
#include <cuda_runtime.h>

// EquivariantLayerNorm, specialized to IRREPS=[(256,0),(128,1),(64,2),(32,3)]
//   dim = 1184, f4-per-row = 296
//   f4 group ranges: g0 [0,64) g1 [64,160) g2 [160,240) g3 [240,296)
//   element counts: 256, 384, 320, 224; scalar block = g0, identity bias map.
//
// FINAL (round-9 optimum): barrier-free, CTA = 128 threads = 4 warps, one
// warp per group (rotated by blockIdx for SMSP balance). Each warp owns up
// to 3 f4 slots per lane, reduces its group's stats via warp butterflies
// (all lanes end with the sum), computes rsqrt locally, scales and stores.
// No smem, no __syncthreads; 1-deep register prefetch; 8 CTAs/SM.
// Verified: 93.2us kernel, DRAM 77%, regs 56. Perturbations that regressed:
// deeper pipeline, proportional strides, atomic queues, 9 CTAs/SM, L2 hints.

#define DIM   1184
#define EPSV  1e-5f

__global__ __launch_bounds__(128) void eln_kernel(const float* __restrict__ x,
                                                  float* __restrict__ out,
                                                  const float* __restrict__ weight,
                                                  const float* __restrict__ bias,
                                                  const int* __restrict__ irrep_idx,
                                                  int nrows) {
    const int t    = threadIdx.x;
    const int warp = t >> 5;
    const int lane = t & 31;
    const int g    = (warp + blockIdx.x) & 3;   // rotated group assignment

    // ---- per-warp group parameters (init only; warp-uniform) ----
    int s0, sz; float inv;
    if (g == 0)      { s0 = 0;   sz = 64; inv = 1.f / 256.f; }
    else if (g == 1) { s0 = 64;  sz = 96; inv = 1.f / 384.f; }
    else if (g == 2) { s0 = 160; sz = 80; inv = 1.f / 320.f; }
    else             { s0 = 240; sz = 56; inv = 1.f / 224.f; }
    const bool isScalar = (g == 0);

    const int  i0 = s0 + lane;                 // always valid
    const bool p1 = (lane + 32) < sz;
    const bool p2 = (lane + 64) < sz;
    const int  i1 = i0 + 32;
    const int  i2 = i0 + 64;

    // ---- one-time init: per-slot weight / bias in registers ----
    float4 w0 = make_float4(0.f,0.f,0.f,0.f), w1 = w0, w2 = w0;
    {
        const int c = 4 * i0;
        w0.x = weight[irrep_idx[c+0]]; w0.y = weight[irrep_idx[c+1]];
        w0.z = weight[irrep_idx[c+2]]; w0.w = weight[irrep_idx[c+3]];
    }
    if (p1) {
        const int c = 4 * i1;
        w1.x = weight[irrep_idx[c+0]]; w1.y = weight[irrep_idx[c+1]];
        w1.z = weight[irrep_idx[c+2]]; w1.w = weight[irrep_idx[c+3]];
    }
    if (p2) {
        const int c = 4 * i2;
        w2.x = weight[irrep_idx[c+0]]; w2.y = weight[irrep_idx[c+1]];
        w2.z = weight[irrep_idx[c+2]]; w2.w = weight[irrep_idx[c+3]];
    }
    float4 b0 = make_float4(0.f,0.f,0.f,0.f), b1 = b0;
    if (isScalar) {   // scalar block = cols [0,256) = g0's two slots, identity map
        b0 = ((const float4*)bias)[i0];
        b1 = ((const float4*)bias)[i1];
    }

    int row = blockIdx.x;
    const int stride = gridDim.x;

    float4 v0 = make_float4(0.f,0.f,0.f,0.f), v1 = v0, v2 = v0;
    if (row < nrows) {
        const float4* xr = (const float4*)(x + (size_t)row * DIM);
        v0 = __ldcs(xr + i0);
        if (p1) v1 = __ldcs(xr + i1);
        if (p2) v2 = __ldcs(xr + i2);
    }

    while (row < nrows) {
        float q = v0.x*v0.x + v0.y*v0.y + v0.z*v0.z + v0.w*v0.w
                + v1.x*v1.x + v1.y*v1.y + v1.z*v1.z + v1.w*v1.w
                + v2.x*v2.x + v2.y*v2.y + v2.z*v2.z + v2.w*v2.w;
        float s = isScalar ? (v0.x + v0.y + v0.z + v0.w +
                              v1.x + v1.y + v1.z + v1.w) : 0.f;

        // Prefetch next row while the shuffles run.
        const int nrow = row + stride;
        float4 nv0 = make_float4(0.f,0.f,0.f,0.f), nv1 = nv0, nv2 = nv0;
        if (nrow < nrows) {
            const float4* nxr = (const float4*)(x + (size_t)nrow * DIM);
            nv0 = __ldcs(nxr + i0);
            if (p1) nv1 = __ldcs(nxr + i1);
            if (p2) nv2 = __ldcs(nxr + i2);
        }

        #pragma unroll
        for (int off = 16; off; off >>= 1) {
            q += __shfl_xor_sync(0xffffffffu, q, off);
            s += __shfl_xor_sync(0xffffffffu, s, off);
        }

        const float m  = s * inv;                       // 0 for non-scalar warps
        const float rn = rsqrtf(q * inv - m * m + EPSV);

        float4* orow = (float4*)(out + (size_t)row * DIM);
        {
            float4 o;
            o.x = (v0.x - m) * rn * w0.x + b0.x;
            o.y = (v0.y - m) * rn * w0.y + b0.y;
            o.z = (v0.z - m) * rn * w0.z + b0.z;
            o.w = (v0.w - m) * rn * w0.w + b0.w;
            __stcs(orow + i0, o);
        }
        if (p1) {
            float4 o;
            o.x = (v1.x - m) * rn * w1.x + b1.x;
            o.y = (v1.y - m) * rn * w1.y + b1.y;
            o.z = (v1.z - m) * rn * w1.z + b1.z;
            o.w = (v1.w - m) * rn * w1.w + b1.w;
            __stcs(orow + i1, o);
        }
        if (p2) {
            float4 o;
            o.x = v2.x * rn * w2.x;                     // slot2 never scalar: m=0, b=0
            o.y = v2.y * rn * w2.y;
            o.z = v2.z * rn * w2.z;
            o.w = v2.w * rn * w2.w;
            __stcs(orow + i2, o);
        }

        v0 = nv0; v1 = nv1; v2 = nv2;
        row = nrow;
    }
}

extern "C" void kernel_launch(void* const* d_in, const int* in_sizes, int n_in,
                              void* d_out, int out_size) {
    const float* x         = (const float*)d_in[0];
    const float* weight    = (const float*)d_in[1];
    const float* bias      = (const float*)d_in[2];
    const int*   irrep_idx = (const int*)  d_in[4];

    const int dim = in_sizes[3];           // 1184
    const int n   = in_sizes[0] / dim;     // 65536 rows

    const int grid = 148 * 8;              // proven optimum: 8 CTAs/SM
    eln_kernel<<<grid, 128>>>(x, (float*)d_out, weight, bias, irrep_idx, n);
}

// round 16
// speedup vs baseline: 1.5598x; 1.0402x over previous
#include <cuda_runtime.h>

// EquivariantLayerNorm, specialized to IRREPS=[(256,0),(128,1),(64,2),(32,3)]
//   dim = 1184, f4-per-row = 296
//   f4 group ranges: g0 [0,64) g1 [64,160) g2 [160,240) g3 [240,296)
//   element counts: 256, 384, 320, 224; scalar block = g0, identity bias map.
//
// Round-9 optimum (barrier-free warp-per-group, rotated assignment, 1-deep
// register prefetch, 8 CTAs/SM) + warp-uniform elimination of the scalar-sum
// butterfly on non-scalar warps (s == 0 there; 5 SHFL + 5 FADD + 7 FADD dead).

#define DIM   1184
#define EPSV  1e-5f

__global__ __launch_bounds__(128) void eln_kernel(const float* __restrict__ x,
                                                  float* __restrict__ out,
                                                  const float* __restrict__ weight,
                                                  const float* __restrict__ bias,
                                                  const int* __restrict__ irrep_idx,
                                                  int nrows) {
    const int t    = threadIdx.x;
    const int warp = t >> 5;
    const int lane = t & 31;
    const int g    = (warp + blockIdx.x) & 3;   // rotated group assignment

    // ---- per-warp group parameters (init only; warp-uniform) ----
    int s0, sz; float inv;
    if (g == 0)      { s0 = 0;   sz = 64; inv = 1.f / 256.f; }
    else if (g == 1) { s0 = 64;  sz = 96; inv = 1.f / 384.f; }
    else if (g == 2) { s0 = 160; sz = 80; inv = 1.f / 320.f; }
    else             { s0 = 240; sz = 56; inv = 1.f / 224.f; }
    const bool isScalar = (g == 0);

    const int  i0 = s0 + lane;                 // always valid
    const bool p1 = (lane + 32) < sz;
    const bool p2 = (lane + 64) < sz;
    const int  i1 = i0 + 32;
    const int  i2 = i0 + 64;

    // ---- one-time init: per-slot weight / bias in registers ----
    float4 w0 = make_float4(0.f,0.f,0.f,0.f), w1 = w0, w2 = w0;
    {
        const int c = 4 * i0;
        w0.x = weight[irrep_idx[c+0]]; w0.y = weight[irrep_idx[c+1]];
        w0.z = weight[irrep_idx[c+2]]; w0.w = weight[irrep_idx[c+3]];
    }
    if (p1) {
        const int c = 4 * i1;
        w1.x = weight[irrep_idx[c+0]]; w1.y = weight[irrep_idx[c+1]];
        w1.z = weight[irrep_idx[c+2]]; w1.w = weight[irrep_idx[c+3]];
    }
    if (p2) {
        const int c = 4 * i2;
        w2.x = weight[irrep_idx[c+0]]; w2.y = weight[irrep_idx[c+1]];
        w2.z = weight[irrep_idx[c+2]]; w2.w = weight[irrep_idx[c+3]];
    }
    float4 b0 = make_float4(0.f,0.f,0.f,0.f), b1 = b0;
    if (isScalar) {   // scalar block = cols [0,256) = g0's two slots, identity map
        b0 = ((const float4*)bias)[i0];
        b1 = ((const float4*)bias)[i1];
    }

    int row = blockIdx.x;
    const int stride = gridDim.x;

    float4 v0 = make_float4(0.f,0.f,0.f,0.f), v1 = v0, v2 = v0;
    if (row < nrows) {
        const float4* xr = (const float4*)(x + (size_t)row * DIM);
        v0 = __ldcs(xr + i0);
        if (p1) v1 = __ldcs(xr + i1);
        if (p2) v2 = __ldcs(xr + i2);
    }

    while (row < nrows) {
        float q = v0.x*v0.x + v0.y*v0.y + v0.z*v0.z + v0.w*v0.w
                + v1.x*v1.x + v1.y*v1.y + v1.z*v1.z + v1.w*v1.w
                + v2.x*v2.x + v2.y*v2.y + v2.z*v2.z + v2.w*v2.w;

        // Prefetch next row while the shuffles run.
        const int nrow = row + stride;
        float4 nv0 = make_float4(0.f,0.f,0.f,0.f), nv1 = nv0, nv2 = nv0;
        if (nrow < nrows) {
            const float4* nxr = (const float4*)(x + (size_t)nrow * DIM);
            nv0 = __ldcs(nxr + i0);
            if (p1) nv1 = __ldcs(nxr + i1);
            if (p2) nv2 = __ldcs(nxr + i2);
        }

        #pragma unroll
        for (int off = 16; off; off >>= 1) {
            q += __shfl_xor_sync(0xffffffffu, q, off);
        }

        float m = 0.f;
        if (isScalar) {                   // warp-uniform: only g0 warps run this
            float s = v0.x + v0.y + v0.z + v0.w +
                      v1.x + v1.y + v1.z + v1.w;
            #pragma unroll
            for (int off = 16; off; off >>= 1) {
                s += __shfl_xor_sync(0xffffffffu, s, off);
            }
            m = s * inv;
        }
        const float rn = rsqrtf(q * inv - m * m + EPSV);

        float4* orow = (float4*)(out + (size_t)row * DIM);
        {
            float4 o;
            o.x = (v0.x - m) * rn * w0.x + b0.x;
            o.y = (v0.y - m) * rn * w0.y + b0.y;
            o.z = (v0.z - m) * rn * w0.z + b0.z;
            o.w = (v0.w - m) * rn * w0.w + b0.w;
            __stcs(orow + i0, o);
        }
        if (p1) {
            float4 o;
            o.x = (v1.x - m) * rn * w1.x + b1.x;
            o.y = (v1.y - m) * rn * w1.y + b1.y;
            o.z = (v1.z - m) * rn * w1.z + b1.z;
            o.w = (v1.w - m) * rn * w1.w + b1.w;
            __stcs(orow + i1, o);
        }
        if (p2) {
            float4 o;
            o.x = v2.x * rn * w2.x;                     // slot2 never scalar: m=0, b=0
            o.y = v2.y * rn * w2.y;
            o.z = v2.z * rn * w2.z;
            o.w = v2.w * rn * w2.w;
            __stcs(orow + i2, o);
        }

        v0 = nv0; v1 = nv1; v2 = nv2;
        row = nrow;
    }
}

extern "C" void kernel_launch(void* const* d_in, const int* in_sizes, int n_in,
                              void* d_out, int out_size) {
    const float* x         = (const float*)d_in[0];
    const float* weight    = (const float*)d_in[1];
    const float* bias      = (const float*)d_in[2];
    const int*   irrep_idx = (const int*)  d_in[4];

    const int dim = in_sizes[3];           // 1184
    const int n   = in_sizes[0] / dim;     // 65536 rows

    const int grid = 148 * 8;              // proven optimum: 8 CTAs/SM
    eln_kernel<<<grid, 128>>>(x, (float*)d_out, weight, bias, irrep_idx, n);
}